// round 6
// baseline (speedup 1.0000x reference)
#include <cuda_runtime.h>
#include <cuda_fp16.h>

#define N_NODES   100000
#define HIDDEN    48
#define N_TRIPLES 2000000
#define ROW_PAD   64          // u/v rows padded to 64 halves = 128 B

typedef unsigned long long u64;

__device__ __align__(16) __half g_u[N_NODES * ROW_PAD];    // fp16 u
__device__ __align__(16) __half g_v[N_NODES * ROW_PAD];    // fp16 v
__device__ __align__(16) float  g_agg[N_NODES * HIDDEN];   // zero-maintained
__device__ __align__(16) float  g_cnt[N_NODES];            // zero-maintained
__device__ __align__(16) float  g_C2[HIDDEN * HIDDEN];
__device__ __align__(16) int4   g_rec[N_TRIPLES];          // {c, n1, n2, w_bits}

// ---------------- f32x2 helpers (Blackwell packed FFMA2) --------------------
__device__ __forceinline__ u64 pack2(float lo, float hi) {
    u64 r; asm("mov.b64 %0, {%1, %2};" : "=l"(r) : "f"(lo), "f"(hi)); return r;
}
__device__ __forceinline__ float2 unpack2(u64 d) {
    float2 r; asm("mov.b64 {%0, %1}, %2;" : "=f"(r.x), "=f"(r.y) : "l"(d)); return r;
}
__device__ __forceinline__ void fma2(u64& d, u64 a, u64 b) {
    asm("fma.rn.f32x2 %0, %1, %2, %0;" : "+l"(d) : "l"(a), "l"(b));
}

// ---------------------------------------------------------------------------
// C2[k][o] = sum_j W3[j][k] * Wu[o][48+j]
// ---------------------------------------------------------------------------
__global__ void prep_kernel(const float* __restrict__ W3,
                            const float* __restrict__ Wu) {
    int i = blockIdx.x * blockDim.x + threadIdx.x;
    if (i < HIDDEN * HIDDEN) {
        int k = i / HIDDEN, o = i % HIDDEN;
        float s = 0.f;
        #pragma unroll
        for (int j = 0; j < HIDDEN; j++)
            s = fmaf(W3[j * HIDDEN + k], Wu[o * 2 * HIDDEN + HIDDEN + j], s);
        g_C2[i] = s;
    }
}

// ---------------------------------------------------------------------------
// Pack per-triple record {c, n1, n2, w} and accumulate center counts.
// (g_cnt is zero on entry: zero-init at load, re-zeroed by final_kernel.)
// ---------------------------------------------------------------------------
__global__ void pack_kernel(const int* __restrict__ idx,
                            const float* __restrict__ d1a,
                            const float* __restrict__ d2a) {
    int t = blockIdx.x * blockDim.x + threadIdx.x;
    if (t < N_TRIPLES) {
        int c  = idx[3 * t];
        int n1 = idx[3 * t + 1];
        int n2 = idx[3 * t + 2];
        float d1 = __ldg(d1a + t);
        float d2 = __ldg(d2a + t);
        float w = 1.0f + 0.3f * (fabsf(d1 - d2) / (fmaxf(d1, d2) + 1e-8f));
        g_rec[t] = make_int4(c, n1, n2, __float_as_int(w));
        asm volatile("red.global.add.f32 [%0], %1;"
                     :: "l"(g_cnt + c), "f"(1.0f) : "memory");
    }
}

// ---------------------------------------------------------------------------
// u[n][o] = h[n]·Wu1[o];  v[n][o] = h[n]·C2[:,o]  -> both fp16, 128B rows.
// blockDim (12, 32); inner loop uses packed f32x2 FMA (8 FFMA2 vs 16 FFMA).
// ---------------------------------------------------------------------------
__global__ void uv_kernel(const float* __restrict__ h,
                          const float* __restrict__ Wu) {
    __shared__ float4 sA[HIDDEN][12];
    __shared__ float4 sC[HIDDEN][12];
    __shared__ float  sh[64][49];

    int tx = threadIdx.x;                  // 0..11
    int ty = threadIdx.y;                  // 0..31
    int tid = ty * 12 + tx;

    for (int i = tid; i < HIDDEN * 12; i += 384) {
        int k = i / 12, c4 = i % 12;
        sA[k][c4] = make_float4(Wu[(4*c4+0) * 2*HIDDEN + k],
                                Wu[(4*c4+1) * 2*HIDDEN + k],
                                Wu[(4*c4+2) * 2*HIDDEN + k],
                                Wu[(4*c4+3) * 2*HIDDEN + k]);
        sC[k][c4] = ((const float4*)g_C2)[k * 12 + c4];
    }
    int rowBase = blockIdx.x * 64;
    for (int i = tid; i < 64 * 12; i += 384) {
        int r = i / 12, c4 = i % 12;
        int row = rowBase + r;
        float4 v = (row < N_NODES) ? ((const float4*)(h + row * HIDDEN))[c4]
                                   : make_float4(0.f, 0.f, 0.f, 0.f);
        sh[r][4*c4+0] = v.x; sh[r][4*c4+1] = v.y;
        sh[r][4*c4+2] = v.z; sh[r][4*c4+3] = v.w;
    }
    __syncthreads();

    int r0 = ty, r1 = ty + 32;
    u64 au0[2] = {0ull, 0ull}, au1[2] = {0ull, 0ull};
    u64 av0[2] = {0ull, 0ull}, av1[2] = {0ull, 0ull};

    union F4U { float4 f; u64 u[2]; };
    #pragma unroll
    for (int k = 0; k < HIDDEN; k++) {
        F4U wa; wa.f = sA[k][tx];
        F4U wc; wc.f = sC[k][tx];
        u64 hh0 = pack2(sh[r0][k], sh[r0][k]);
        u64 hh1 = pack2(sh[r1][k], sh[r1][k]);
        fma2(au0[0], hh0, wa.u[0]); fma2(au0[1], hh0, wa.u[1]);
        fma2(au1[0], hh1, wa.u[0]); fma2(au1[1], hh1, wa.u[1]);
        fma2(av0[0], hh0, wc.u[0]); fma2(av0[1], hh0, wc.u[1]);
        fma2(av1[0], hh1, wc.u[0]); fma2(av1[1], hh1, wc.u[1]);
    }

    int row0 = rowBase + r0, row1 = rowBase + r1;
    if (row0 < N_NODES) {
        float2 a = unpack2(au0[0]), b = unpack2(au0[1]);
        float2 c = unpack2(av0[0]), d = unpack2(av0[1]);
        union { __half2 h2[2]; uint2 u; } cu, cv;
        cu.h2[0] = __floats2half2_rn(a.x, a.y); cu.h2[1] = __floats2half2_rn(b.x, b.y);
        cv.h2[0] = __floats2half2_rn(c.x, c.y); cv.h2[1] = __floats2half2_rn(d.x, d.y);
        ((uint2*)(g_u + row0 * ROW_PAD))[tx] = cu.u;
        ((uint2*)(g_v + row0 * ROW_PAD))[tx] = cv.u;
    }
    if (row1 < N_NODES) {
        float2 a = unpack2(au1[0]), b = unpack2(au1[1]);
        float2 c = unpack2(av1[0]), d = unpack2(av1[1]);
        union { __half2 h2[2]; uint2 u; } cu, cv;
        cu.h2[0] = __floats2half2_rn(a.x, a.y); cu.h2[1] = __floats2half2_rn(b.x, b.y);
        cv.h2[0] = __floats2half2_rn(c.x, c.y); cv.h2[1] = __floats2half2_rn(d.x, d.y);
        ((uint2*)(g_u + row1 * ROW_PAD))[tx] = cu.u;
        ((uint2*)(g_v + row1 * ROW_PAD))[tx] = cv.u;
    }
}

// ---------------------------------------------------------------------------
// Per-triple: rec + 3x fp16 one-line gathers + hadd2 + leaky*w + fp32 v4 RED.
// ---------------------------------------------------------------------------
__device__ __forceinline__ void process_triple(int t, int j) {
    int4 r = __ldg(&g_rec[t]);
    float w = __int_as_float(r.w);
    if (j < 12) {
        uint2 au = __ldg((const uint2*)(g_u + r.x * ROW_PAD) + j);
        uint2 a1 = __ldg((const uint2*)(g_v + r.y * ROW_PAD) + j);
        uint2 a2 = __ldg((const uint2*)(g_v + r.z * ROW_PAD) + j);
        __half2 s0 = __hadd2(*(__half2*)&a1.x, *(__half2*)&a2.x);
        __half2 s1 = __hadd2(*(__half2*)&a1.y, *(__half2*)&a2.y);
        s0 = __hadd2(s0, *(__half2*)&au.x);
        s1 = __hadd2(s1, *(__half2*)&au.y);
        float2 f0 = __half22float2(s0);
        float2 f1 = __half22float2(s1);
        float w01 = 0.01f * w;
        float dx = fmaf(fminf(f0.x, 0.f), w01, fmaxf(f0.x, 0.f) * w);
        float dy = fmaf(fminf(f0.y, 0.f), w01, fmaxf(f0.y, 0.f) * w);
        float dz = fmaf(fminf(f1.x, 0.f), w01, fmaxf(f1.x, 0.f) * w);
        float dw = fmaf(fminf(f1.y, 0.f), w01, fmaxf(f1.y, 0.f) * w);
        float* dst = g_agg + r.x * HIDDEN + 4 * j;
        asm volatile("red.global.add.v4.f32 [%0], {%1, %2, %3, %4};"
                     :: "l"(dst), "f"(dx), "f"(dy), "f"(dz), "f"(dw)
                     : "memory");
    }
}

__global__ void __launch_bounds__(256) triple_kernel() {
    int gtid = blockIdx.x * blockDim.x + threadIdx.x;
    int warpId = gtid >> 5;
    int nWarps = (gridDim.x * blockDim.x) >> 5;
    int lane = threadIdx.x & 31;
    int half = lane >> 4;
    int j = lane & 15;

    for (int base = warpId * 4; base < N_TRIPLES; base += nWarps * 4) {
        process_triple(base + half, j);
        process_triple(base + 2 + half, j);
    }
}

// ---------------------------------------------------------------------------
// out = LayerNorm(h + agg / sqrt(max(cnt,1))); re-zeroes agg/cnt for the next
// replay. Fully float4-vectorized: lanes 0..11 of each 16-lane group carry a
// float4; lanes 12..15 contribute zeros to the reductions.
// ---------------------------------------------------------------------------
__global__ void final_kernel(const float* __restrict__ h,
                             const float* __restrict__ gamma,
                             const float* __restrict__ beta,
                             float* __restrict__ out) {
    int tx = threadIdx.x;  // 0..15
    int ty = threadIdx.y;  // 0..15
    int row = blockIdx.x * 16 + ty;
    bool act = tx < 12;

    float rs = rsqrtf(fmaxf(g_cnt[row], 1.0f));
    if (tx == 0) g_cnt[row] = 0.f;

    int b4 = row * 12 + tx;
    float4 x = make_float4(0.f, 0.f, 0.f, 0.f);
    if (act) {
        float4 hv = __ldg((const float4*)h + b4);
        float4 av = ((const float4*)g_agg)[b4];
        x.x = fmaf(av.x, rs, hv.x);
        x.y = fmaf(av.y, rs, hv.y);
        x.z = fmaf(av.z, rs, hv.z);
        x.w = fmaf(av.w, rs, hv.w);
        ((float4*)g_agg)[b4] = make_float4(0.f, 0.f, 0.f, 0.f);
    }

    float s = x.x + x.y + x.z + x.w;
    #pragma unroll
    for (int m = 8; m; m >>= 1) s += __shfl_xor_sync(0xffffffffu, s, m);
    float mu = s * (1.f / 48.f);

    float e0 = x.x - mu, e1 = x.y - mu, e2 = x.z - mu, e3 = x.w - mu;
    float q = act ? (e0*e0 + e1*e1 + e2*e2 + e3*e3) : 0.f;
    #pragma unroll
    for (int m = 8; m; m >>= 1) q += __shfl_xor_sync(0xffffffffu, q, m);
    float inv = rsqrtf(q * (1.f / 48.f) + 1e-5f);

    if (act) {
        float4 g = __ldg((const float4*)gamma + tx);
        float4 b = __ldg((const float4*)beta + tx);
        float4 o;
        o.x = fmaf(e0 * inv, g.x, b.x);
        o.y = fmaf(e1 * inv, g.y, b.y);
        o.z = fmaf(e2 * inv, g.z, b.z);
        o.w = fmaf(e3 * inv, g.w, b.w);
        ((float4*)out)[b4] = o;
    }
}

// ---------------------------------------------------------------------------
extern "C" void kernel_launch(void* const* d_in, const int* in_sizes, int n_in,
                              void* d_out, int out_size) {
    const float* h     = (const float*)d_in[0];
    const int*   idx   = (const int*)d_in[1];
    const float* d1    = (const float*)d_in[2];
    const float* d2    = (const float*)d_in[3];
    const float* W3    = (const float*)d_in[4];
    const float* Wu    = (const float*)d_in[5];
    const float* gamma = (const float*)d_in[6];
    const float* beta  = (const float*)d_in[7];
    float* out = (float*)d_out;

    static cudaStream_t s2 = nullptr;
    static cudaEvent_t evF = nullptr, evJ = nullptr;
    if (!s2) {
        cudaStreamCreateWithFlags(&s2, cudaStreamNonBlocking);
        cudaEventCreateWithFlags(&evF, cudaEventDisableTiming);
        cudaEventCreateWithFlags(&evJ, cudaEventDisableTiming);
    }

    // fork: pack runs concurrently with prep+uv
    cudaEventRecord(evF, 0);
    cudaStreamWaitEvent(s2, evF, 0);
    pack_kernel<<<(N_TRIPLES + 255) / 256, 256, 0, s2>>>(idx, d1, d2);
    cudaEventRecord(evJ, s2);

    prep_kernel<<<(HIDDEN * HIDDEN + 255) / 256, 256>>>(W3, Wu);
    uv_kernel<<<(N_NODES + 63) / 64, dim3(12, 32)>>>(h, Wu);

    cudaStreamWaitEvent(0, evJ, 0);   // join
    triple_kernel<<<4096, 256>>>();
    final_kernel<<<(N_NODES + 15) / 16, dim3(16, 16)>>>(h, gamma, beta, out);
}